// round 11
// baseline (speedup 1.0000x reference)
#include <cuda_runtime.h>
#include <math.h>
#include <stdint.h>
#include <mma.h>

using namespace nvcuda;

#define TT    1024
#define DIM   512
#define NG    8
#define NE    8
#define NPAIR 64
#define HDIM  1024

__device__ int   d_cnt[NPAIR];
__device__ int   d_tok[NPAIR][TT];
__device__ int   d_asg[NPAIR][TT];
__device__ int   d_pid[TT * 4];        // pair id per assignment (for bias in combine)
__device__ float d_w[TT * 4];
__device__ float d_H[TT * 4][HDIM];
__device__ float d_Yp[2][TT * 4][DIM]; // split-K partials for layer 2
__device__ __align__(16) float d_zero[DIM];  // static zero row for invalid gathers

__device__ __forceinline__ uint32_t smem_u32(const void* p) {
    uint32_t a;
    asm("{ .reg .u64 t; cvta.to.shared.u64 t, %1; cvt.u32.u64 %0, t; }" : "=r"(a) : "l"(p));
    return a;
}
__device__ __forceinline__ void cp16(uint32_t s, const void* g) {
    asm volatile("cp.async.cg.shared.global [%0], [%1], 16;" :: "r"(s), "l"(g));
}
#define CP_COMMIT() asm volatile("cp.async.commit_group;" ::: "memory")
#define CP_WAIT1()  asm volatile("cp.async.wait_group 1;" ::: "memory")
#define CP_WAIT0()  asm volatile("cp.async.wait_group 0;" ::: "memory")

// Both A and B enter the MMA as raw fp32 bits (HW tf32 truncation, bias ~ -2^-11
// per operand): correct the systematic scale (1+2^-11)^2 in the epilogue.
#define CORR2 1.000976799f

// ---------------- kernel 0: reset pair counters ----------------
__global__ void zero_cnt_kernel() {
    if (threadIdx.x < NPAIR) d_cnt[threadIdx.x] = 0;
}

// ---------------- kernel 1: routing (one warp per token) ----------------
__global__ void route_kernel(const float* __restrict__ x,
                             const float* __restrict__ g1,
                             const float* __restrict__ g2) {
    int t = (blockIdx.x * blockDim.x + threadIdx.x) >> 5;
    int lane = threadIdx.x & 31;
    if (t >= TT) return;
    const float* xt = x + (size_t)t * DIM;

    float a[NG];
#pragma unroll
    for (int g = 0; g < NG; g++) a[g] = 0.f;
    for (int i = lane; i < DIM; i += 32) {
        float xv = xt[i];
        const float* gp = g1 + (size_t)i * NG;
#pragma unroll
        for (int g = 0; g < NG; g++) a[g] += xv * gp[g];
    }
#pragma unroll
    for (int off = 16; off; off >>= 1)
#pragma unroll
        for (int g = 0; g < NG; g++) a[g] += __shfl_xor_sync(0xffffffffu, a[g], off);

    int i1 = 0; float v1 = a[0];
#pragma unroll
    for (int g = 1; g < NG; g++) if (a[g] > v1) { v1 = a[g]; i1 = g; }
    int i2 = -1; float v2 = -1e30f;
#pragma unroll
    for (int g = 0; g < NG; g++) if (g != i1 && a[g] > v2) { v2 = a[g]; i2 = g; }
    float e2 = expf(v2 - v1);
    float inv = 1.f / (1.f + e2);
    int   gs[2]  = { i1, i2 };
    float c1w[2] = { inv, e2 * inv };

    float b[2 * NE];
#pragma unroll
    for (int q = 0; q < 2 * NE; q++) b[q] = 0.f;
    const float* p0base = g2 + (size_t)gs[0] * DIM * NE;
    const float* p1base = g2 + (size_t)gs[1] * DIM * NE;
    for (int i = lane; i < DIM; i += 32) {
        float xv = xt[i];
        const float* p0 = p0base + (size_t)i * NE;
        const float* p1 = p1base + (size_t)i * NE;
#pragma unroll
        for (int e = 0; e < NE; e++) { b[e] += xv * p0[e]; b[NE + e] += xv * p1[e]; }
    }
#pragma unroll
    for (int off = 16; off; off >>= 1)
#pragma unroll
        for (int q = 0; q < 2 * NE; q++) b[q] += __shfl_xor_sync(0xffffffffu, b[q], off);

    if (lane == 0) {
#pragma unroll
        for (int r = 0; r < 2; r++) {
            int j1 = 0; float u1 = b[r * NE + 0];
#pragma unroll
            for (int e = 1; e < NE; e++) if (b[r * NE + e] > u1) { u1 = b[r * NE + e]; j1 = e; }
            int j2 = -1; float u2 = -1e30f;
#pragma unroll
            for (int e = 0; e < NE; e++) if (e != j1 && b[r * NE + e] > u2) { u2 = b[r * NE + e]; j2 = e; }
            float f2   = expf(u2 - u1);
            float inv2 = 1.f / (1.f + f2);
            int   pe[2]  = { j1, j2 };
            float c2w[2] = { inv2, f2 * inv2 };
            int g = gs[r];
#pragma unroll
            for (int rr = 0; rr < 2; rr++) {
                int pair = g * NE + pe[rr];
                int slot = r * 2 + rr;
                int pos  = atomicAdd(&d_cnt[pair], 1);
                d_tok[pair][pos] = t;
                d_asg[pair][pos] = t * 4 + slot;
                d_w[t * 4 + slot] = c1w[r] * c2w[rr];
                d_pid[t * 4 + slot] = pair;
            }
        }
    }
}

// ---------------- WMMA tf32 grouped GEMM: full cp.async pipeline ---------------
// Per CTA: (pair, 128-col n-tile[, K-half]). BM=64, BN=128, BK=32, KT=512/CTA.
// 256 threads = 8 warps in 2x4 grid, warp tile 32x32. BOTH A (gathered rows,
// via per-row pointers; invalid rows -> d_zero) and B staged through a 3-stage
// cp.async.cg rotation: ONE __syncthreads per k-stage, no LDG/cvt/STS chain.
// HW tf32 truncation on both operands; CORR2 scale fix in epilogue.
// smem (dynamic, bytes):
//   0:     A bufs 3 x 64x36 f  (27648)
//   27648: B bufs 3 x 32x132 f (50688)  [aliased as Cs 64x132 in epilogue]
//   78336: bsm[128] | 78848: rp[64] ptr | 79360: atb[64] int  -> 79616
#define AB_OFF 0
#define BB_OFF 27648
#define SMEM_DYN 79616

template <int KT, int KFULL, int NTOT, bool RELU, bool SPLIT>
__global__ __launch_bounds__(256, 2) void moe_gemm_wmma(const float* __restrict__ Xg,
                                                        const float* __restrict__ Wt,
                                                        const float* __restrict__ bias) {
    constexpr int BM = 64, BN = 128, BK = 32, NKC = KT / BK;
    constexpr int LDA = 36, LDB = 132, LDC = 132;
    const int pair  = blockIdx.y;
    const int count = d_cnt[pair];
    if (count == 0) return;
    const int n0    = blockIdx.x * BN;
    const int kbase = SPLIT ? (int)blockIdx.z * KT : 0;

    const float* Xsrc = SPLIT ? &d_H[0][0] : Xg;
    float*       Out  = SPLIT ? &d_Yp[blockIdx.z][0][0] : &d_H[0][0];
    const int*   rows = SPLIT ? d_asg[pair] : d_tok[pair];
    const float* Wp   = Wt + (size_t)pair * KFULL * NTOT + (size_t)kbase * NTOT + n0;
    const float* bp   = bias + (size_t)pair * NTOT + n0;

    extern __shared__ __align__(16) char smem[];
    float* const Abase = (float*)(smem + AB_OFF);
    float* const Bbase = (float*)(smem + BB_OFF);
    float* const bsm   = (float*)(smem + 78336);
    const float** rp   = (const float**)(smem + 78848);
    int*   atb         = (int*)(smem + 79360);
    const uint32_t sb  = smem_u32(smem);

    const int tid = threadIdx.x;
    const int wid = tid >> 5;
    const int wm  = wid >> 2;     // 0..1 (32-row half)
    const int wn  = wid & 3;      // 0..3 (32-col quarter)

    if (!SPLIT && tid < BN) bsm[tid] = bp[tid];

    // staging coords: A 2 chunks/thread over 64x32, B 4 chunks/thread over 32x128
    int ar[2], ak[2], br[4], bc[4];
#pragma unroll
    for (int i = 0; i < 2; i++) {
        int q = tid + i * 256;
        ar[i] = q >> 3; ak[i] = (q & 7) * 4;
    }
#pragma unroll
    for (int i = 0; i < 4; i++) {
        int q = tid + i * 256;
        br[i] = q >> 5; bc[i] = (q & 31) * 4;
    }

    for (int m0 = 0; m0 < count; m0 += BM) {
        if (tid < BM) {
            int m = m0 + tid;
            rp[tid]  = (m < count) ? (Xsrc + (size_t)rows[m] * KFULL + kbase) : d_zero;
            atb[tid] = (m < count) ? d_asg[pair][m] : 0;
        }
        __syncthreads();

        const float* arow[2];
#pragma unroll
        for (int i = 0; i < 2; i++) arow[i] = rp[ar[i]];

        wmma::fragment<wmma::accumulator, 16, 16, 8, float> acc[2][2];
#pragma unroll
        for (int i = 0; i < 2; i++)
#pragma unroll
            for (int j = 0; j < 2; j++) wmma::fill_fragment(acc[i][j], 0.f);

        // prologue: issue stages 0,1
#pragma unroll
        for (int s = 0; s < 2; s++) {
            const int k0 = s * BK;
            uint32_t ab = sb + AB_OFF + s * 9216;
            uint32_t bb = sb + BB_OFF + s * 16896;
#pragma unroll
            for (int i = 0; i < 2; i++)
                cp16(ab + (uint32_t)(ar[i] * LDA + ak[i]) * 4, arow[i] + k0 + ak[i]);
#pragma unroll
            for (int i = 0; i < 4; i++)
                cp16(bb + (uint32_t)(br[i] * LDB + bc[i]) * 4, Wp + (size_t)(k0 + br[i]) * NTOT + bc[i]);
            CP_COMMIT();
        }

        for (int c = 0; c < NKC; c++) {
            CP_WAIT1();              // stage c arrived
            __syncthreads();

            if (c + 2 < NKC) {       // issue stage c+2 into buffer (c+2)%3 (unused)
                const int k0 = (c + 2) * BK;
                uint32_t ab = sb + AB_OFF + ((c + 2) % 3) * 9216;
                uint32_t bb = sb + BB_OFF + ((c + 2) % 3) * 16896;
#pragma unroll
                for (int i = 0; i < 2; i++)
                    cp16(ab + (uint32_t)(ar[i] * LDA + ak[i]) * 4, arow[i] + k0 + ak[i]);
#pragma unroll
                for (int i = 0; i < 4; i++)
                    cp16(bb + (uint32_t)(br[i] * LDB + bc[i]) * 4, Wp + (size_t)(k0 + br[i]) * NTOT + bc[i]);
            }
            CP_COMMIT();

            const float* Ac = Abase + (c % 3) * 2304;
            const float* Bc = Bbase + (c % 3) * 4224;
#pragma unroll
            for (int kk = 0; kk < BK; kk += 8) {
                wmma::fragment<wmma::matrix_a, 16, 16, 8, wmma::precision::tf32, wmma::row_major> af[2];
                wmma::fragment<wmma::matrix_b, 16, 16, 8, wmma::precision::tf32, wmma::row_major> bf[2];
#pragma unroll
                for (int i = 0; i < 2; i++)
                    wmma::load_matrix_sync(af[i], Ac + (wm * 32 + i * 16) * LDA + kk, LDA);
#pragma unroll
                for (int j = 0; j < 2; j++)
                    wmma::load_matrix_sync(bf[j], Bc + kk * LDB + wn * 32 + j * 16, LDB);
#pragma unroll
                for (int i = 0; i < 2; i++)
#pragma unroll
                    for (int j = 0; j < 2; j++)
                        wmma::mma_sync(acc[i][j], af[i], bf[j], acc[i][j]);
            }
        }

        // epilogue: reuse B pool as Cs
        CP_WAIT0();
        __syncthreads();
        float* const Cs = Bbase;
#pragma unroll
        for (int i = 0; i < 2; i++)
#pragma unroll
            for (int j = 0; j < 2; j++)
                wmma::store_matrix_sync(Cs + (wm * 32 + i * 16) * LDC + wn * 32 + j * 16,
                                        acc[i][j], LDC, wmma::mem_row_major);
        __syncthreads();

#pragma unroll
        for (int it = 0; it < 8; it++) {
            int f = tid + it * 256;           // float4 index over 64x128
            int row = f >> 5;
            int col = (f & 31) * 4;
            int m = m0 + row;
            if (m < count) {
                const float* cr = Cs + row * LDC + col;
                float4 v;
                if (SPLIT) {
                    v.x = cr[0] * CORR2; v.y = cr[1] * CORR2;
                    v.z = cr[2] * CORR2; v.w = cr[3] * CORR2;
                } else {
                    v.x = cr[0] * CORR2 + bsm[col + 0];
                    v.y = cr[1] * CORR2 + bsm[col + 1];
                    v.z = cr[2] * CORR2 + bsm[col + 2];
                    v.w = cr[3] * CORR2 + bsm[col + 3];
                    if (RELU) {
                        v.x = fmaxf(v.x, 0.f); v.y = fmaxf(v.y, 0.f);
                        v.z = fmaxf(v.z, 0.f); v.w = fmaxf(v.w, 0.f);
                    }
                }
                *reinterpret_cast<float4*>(Out + (size_t)atb[row] * NTOT + n0 + col) = v;
            }
        }
        __syncthreads();
    }
}

// ---------------- kernel 4: reduce split-K halves + bias, weighted combine ----
__global__ void combine_kernel(const float* __restrict__ b2, float* __restrict__ out) {
    int t = blockIdx.x;
    float w[4];
    const float* bb[4];
#pragma unroll
    for (int s = 0; s < 4; s++) {
        w[s]  = d_w[t * 4 + s];
        bb[s] = b2 + (size_t)d_pid[t * 4 + s] * DIM;
    }
    for (int i = threadIdx.x; i < DIM; i += blockDim.x) {
        float acc = 0.f;
#pragma unroll
        for (int s = 0; s < 4; s++) {
            int asg = t * 4 + s;
            acc += w[s] * (d_Yp[0][asg][i] + d_Yp[1][asg][i] + bb[s][i]);
        }
        out[(size_t)t * DIM + i] = acc;
    }
}

// ---------------- launch ----------------
extern "C" void kernel_launch(void* const* d_in, const int* in_sizes, int n_in,
                              void* d_out, int out_size) {
    const float* x  = (const float*)d_in[0];
    const float* g1 = (const float*)d_in[1];
    const float* g2 = (const float*)d_in[2];
    const float* W1 = (const float*)d_in[3];
    const float* b1 = (const float*)d_in[4];
    const float* W2 = (const float*)d_in[5];
    const float* b2 = (const float*)d_in[6];
    float* out = (float*)d_out;

    cudaFuncSetAttribute(moe_gemm_wmma<DIM, DIM, HDIM, true, false>,
                         cudaFuncAttributeMaxDynamicSharedMemorySize, SMEM_DYN);
    cudaFuncSetAttribute(moe_gemm_wmma<DIM, HDIM, DIM, false, true>,
                         cudaFuncAttributeMaxDynamicSharedMemorySize, SMEM_DYN);

    zero_cnt_kernel<<<1, 64>>>();
    route_kernel<<<(TT * 32) / 128, 128>>>(x, g1, g2);
    // layer 1: [count,512] @ [512,1024] + b1, relu -> d_H            (512 CTAs)
    moe_gemm_wmma<DIM, DIM, HDIM, true, false>
        <<<dim3(HDIM / 128, NPAIR, 1), 256, SMEM_DYN>>>(x, W1, b1);
    // layer 2: [count,1024] @ [1024,512], split-K x2 -> d_Yp         (512 CTAs)
    moe_gemm_wmma<DIM, HDIM, DIM, false, true>
        <<<dim3(DIM / 128, NPAIR, 2), 256, SMEM_DYN>>>(x, W2, b2);
    combine_kernel<<<TT, 128>>>(b2, out);
}

// round 14
// speedup vs baseline: 1.1395x; 1.1395x over previous
#include <cuda_runtime.h>
#include <math.h>
#include <stdint.h>
#include <mma.h>

using namespace nvcuda;

#define TT    1024
#define DIM   512
#define NG    8
#define NE    8
#define NPAIR 64
#define HDIM  1024

__device__ int   d_cnt[NPAIR];
__device__ int   d_tok[NPAIR][TT];
__device__ int   d_asg[NPAIR][TT];
__device__ int   d_pid[TT * 4];        // pair id per assignment (for bias in combine)
__device__ float d_w[TT * 4];
__device__ float d_H[TT * 4][HDIM];
__device__ float d_Yp[2][TT * 4][DIM]; // split-K partials for layer 2

// round-to-nearest tf32 conversion (unbiased)
__device__ __forceinline__ float tf32r(float v) {
    uint32_t r;
    asm("cvt.rna.tf32.f32 %0, %1;" : "=r"(r) : "f"(v));
    return __uint_as_float(r);
}
__device__ __forceinline__ uint32_t smem_u32(const void* p) {
    uint32_t a;
    asm("{ .reg .u64 t; cvta.to.shared.u64 t, %1; cvt.u32.u64 %0, t; }" : "=r"(a) : "l"(p));
    return a;
}
__device__ __forceinline__ void cp16(uint32_t s, const void* g) {
    asm volatile("cp.async.cg.shared.global [%0], [%1], 16;" :: "r"(s), "l"(g));
}
#define CP_COMMIT() asm volatile("cp.async.commit_group;" ::: "memory")
#define CP_WAIT1()  asm volatile("cp.async.wait_group 1;" ::: "memory")
#define CP_WAIT0()  asm volatile("cp.async.wait_group 0;" ::: "memory")

// B enters the MMA as raw fp32 bits (HW tf32 truncation, bias ~ -2^-11):
// correct the systematic scale in the epilogue. A is rna-rounded (unbiased).
#define CORR 1.00048828125f

// ---------------- kernel 0: reset pair counters ----------------
__global__ void zero_cnt_kernel() {
    if (threadIdx.x < NPAIR) d_cnt[threadIdx.x] = 0;
}

// ---------------- kernel 1: routing (one warp per token) ----------------
__global__ void route_kernel(const float* __restrict__ x,
                             const float* __restrict__ g1,
                             const float* __restrict__ g2) {
    int t = (blockIdx.x * blockDim.x + threadIdx.x) >> 5;
    int lane = threadIdx.x & 31;
    if (t >= TT) return;
    const float* xt = x + (size_t)t * DIM;

    float a[NG];
#pragma unroll
    for (int g = 0; g < NG; g++) a[g] = 0.f;
    for (int i = lane; i < DIM; i += 32) {
        float xv = xt[i];
        const float* gp = g1 + (size_t)i * NG;
#pragma unroll
        for (int g = 0; g < NG; g++) a[g] += xv * gp[g];
    }
#pragma unroll
    for (int off = 16; off; off >>= 1)
#pragma unroll
        for (int g = 0; g < NG; g++) a[g] += __shfl_xor_sync(0xffffffffu, a[g], off);

    int i1 = 0; float v1 = a[0];
#pragma unroll
    for (int g = 1; g < NG; g++) if (a[g] > v1) { v1 = a[g]; i1 = g; }
    int i2 = -1; float v2 = -1e30f;
#pragma unroll
    for (int g = 0; g < NG; g++) if (g != i1 && a[g] > v2) { v2 = a[g]; i2 = g; }
    float e2 = expf(v2 - v1);
    float inv = 1.f / (1.f + e2);
    int   gs[2]  = { i1, i2 };
    float c1w[2] = { inv, e2 * inv };

    float b[2 * NE];
#pragma unroll
    for (int q = 0; q < 2 * NE; q++) b[q] = 0.f;
    const float* p0base = g2 + (size_t)gs[0] * DIM * NE;
    const float* p1base = g2 + (size_t)gs[1] * DIM * NE;
    for (int i = lane; i < DIM; i += 32) {
        float xv = xt[i];
        const float* p0 = p0base + (size_t)i * NE;
        const float* p1 = p1base + (size_t)i * NE;
#pragma unroll
        for (int e = 0; e < NE; e++) { b[e] += xv * p0[e]; b[NE + e] += xv * p1[e]; }
    }
#pragma unroll
    for (int off = 16; off; off >>= 1)
#pragma unroll
        for (int q = 0; q < 2 * NE; q++) b[q] += __shfl_xor_sync(0xffffffffu, b[q], off);

    if (lane == 0) {
#pragma unroll
        for (int r = 0; r < 2; r++) {
            int j1 = 0; float u1 = b[r * NE + 0];
#pragma unroll
            for (int e = 1; e < NE; e++) if (b[r * NE + e] > u1) { u1 = b[r * NE + e]; j1 = e; }
            int j2 = -1; float u2 = -1e30f;
#pragma unroll
            for (int e = 0; e < NE; e++) if (e != j1 && b[r * NE + e] > u2) { u2 = b[r * NE + e]; j2 = e; }
            float f2   = expf(u2 - u1);
            float inv2 = 1.f / (1.f + f2);
            int   pe[2]  = { j1, j2 };
            float c2w[2] = { inv2, f2 * inv2 };
            int g = gs[r];
#pragma unroll
            for (int rr = 0; rr < 2; rr++) {
                int pair = g * NE + pe[rr];
                int slot = r * 2 + rr;
                int pos  = atomicAdd(&d_cnt[pair], 1);
                d_tok[pair][pos] = t;
                d_asg[pair][pos] = t * 4 + slot;
                d_w[t * 4 + slot] = c1w[r] * c2w[rr];
                d_pid[t * 4 + slot] = pair;
            }
        }
    }
}

// ---------- WMMA tf32 grouped GEMM: 4 warps, warp tile 32x64 -------------------
// Per CTA: (pair, 128-col n-tile[, K-half]). BM=64, BN=128, BK=32, KT=512/CTA.
// 128 threads = 4 warps in 2x2 grid, warp tile 32x64: per kk-step 6 frag loads /
// 8 MMAs with 8 independent accumulators. B staged via 3-stage cp.async.cg (HW
// tf32 truncation, CORR in epilogue); A via register prefetch + rna cvt.
// One __syncthreads per k-stage.
// smem (dynamic): A 2x64x36f (18432) | B 3x32x132f (50688, aliased Cs 64x132) |
//                 bsm[128] | rp[64] ptr | atb[64] int -> 70400
#define AB_OFF 0
#define BB_OFF 18432
#define SMEM_DYN 70400

template <int KT, int KFULL, int NTOT, bool RELU, bool SPLIT>
__global__ __launch_bounds__(128, 3) void moe_gemm_wmma(const float* __restrict__ Xg,
                                                        const float* __restrict__ Wt,
                                                        const float* __restrict__ bias) {
    constexpr int BM = 64, BN = 128, BK = 32, NKC = KT / BK;
    constexpr int LDA = 36, LDB = 132, LDC = 132;
    const int pair  = blockIdx.y;
    const int count = d_cnt[pair];
    if (count == 0) return;
    const int n0    = blockIdx.x * BN;
    const int kbase = SPLIT ? (int)blockIdx.z * KT : 0;

    const float* Xsrc = SPLIT ? &d_H[0][0] : Xg;
    float*       Out  = SPLIT ? &d_Yp[blockIdx.z][0][0] : &d_H[0][0];
    const int*   rows = SPLIT ? d_asg[pair] : d_tok[pair];
    const float* Wp   = Wt + (size_t)pair * KFULL * NTOT + (size_t)kbase * NTOT + n0;
    const float* bp   = bias + (size_t)pair * NTOT + n0;

    extern __shared__ __align__(16) char smem[];
    float* const Abase = (float*)(smem + AB_OFF);
    float* const Bbase = (float*)(smem + BB_OFF);
    float* const bsm   = (float*)(smem + 69120);
    const float** rp   = (const float**)(smem + 69632);
    int*   atb         = (int*)(smem + 70144);
    const uint32_t sb  = smem_u32(smem);

    const int tid = threadIdx.x;
    const int wid = tid >> 5;
    const int wm  = wid >> 1;     // 0..1 (32-row half)
    const int wn  = wid & 1;      // 0..1 (64-col half)

    if (!SPLIT) bsm[tid] = bp[tid];

    // staging coords: A 4 chunks/thread over 64x32, B 8 chunks/thread over 32x128
    int ar[4], ak[4];
#pragma unroll
    for (int i = 0; i < 4; i++) {
        int q = tid + i * 128;
        ar[i] = q >> 3; ak[i] = (q & 7) * 4;
    }
    const int brr = tid >> 5;         // base row 0..3 (+4 rows per chunk pair)
    const int bcc = (tid & 31) * 4;   // col

    for (int m0 = 0; m0 < count; m0 += BM) {
        if (tid < BM) {
            int m = m0 + tid;
            rp[tid]  = (m < count) ? (Xsrc + (size_t)rows[m] * KFULL + kbase) : (const float*)0;
            atb[tid] = (m < count) ? d_asg[pair][m] : 0;
        }
        __syncthreads();

        const float* arow[4];
#pragma unroll
        for (int i = 0; i < 4; i++) arow[i] = rp[ar[i]];

        wmma::fragment<wmma::accumulator, 16, 16, 8, float> acc[2][4];
#pragma unroll
        for (int i = 0; i < 2; i++)
#pragma unroll
            for (int j = 0; j < 4; j++) wmma::fill_fragment(acc[i][j], 0.f);

        // B prologue: issue stages 0,1 via cp.async (8 chunks each)
#pragma unroll
        for (int s = 0; s < 2; s++) {
            uint32_t base = sb + BB_OFF + s * 16896;
            const int k0 = s * BK;
#pragma unroll
            for (int i = 0; i < 8; i++) {
                int r = brr + i * 4;
                cp16(base + (uint32_t)(r * LDB + bcc) * 4, Wp + (size_t)(k0 + r) * NTOT + bcc);
            }
            CP_COMMIT();
        }
        // A prefetch stage 0
        float4 pa[4];
#pragma unroll
        for (int i = 0; i < 4; i++) {
            pa[i] = make_float4(0.f, 0.f, 0.f, 0.f);
            if (arow[i]) pa[i] = *reinterpret_cast<const float4*>(arow[i] + ak[i]);
        }

        for (int c = 0; c < NKC; c++) {
            // commit A(c) to its double buffer
            float* Ac = Abase + (c & 1) * 2304;
#pragma unroll
            for (int i = 0; i < 4; i++) {
                float* a = Ac + ar[i] * LDA + ak[i];
                a[0] = tf32r(pa[i].x); a[1] = tf32r(pa[i].y);
                a[2] = tf32r(pa[i].z); a[3] = tf32r(pa[i].w);
            }
            CP_WAIT1();              // B stage c arrived
            __syncthreads();         // A(c) + B(c) visible to all

            if (c + 2 < NKC) {       // issue B stage c+2
                uint32_t base = sb + BB_OFF + ((c + 2) % 3) * 16896;
                const int k0 = (c + 2) * BK;
#pragma unroll
                for (int i = 0; i < 8; i++) {
                    int r = brr + i * 4;
                    cp16(base + (uint32_t)(r * LDB + bcc) * 4, Wp + (size_t)(k0 + r) * NTOT + bcc);
                }
            }
            CP_COMMIT();
            if (c + 1 < NKC) {       // A prefetch stage c+1
                const int kn = (c + 1) * BK;
#pragma unroll
                for (int i = 0; i < 4; i++) {
                    pa[i] = make_float4(0.f, 0.f, 0.f, 0.f);
                    if (arow[i]) pa[i] = *reinterpret_cast<const float4*>(arow[i] + kn + ak[i]);
                }
            }

            const float* Bc = Bbase + (c % 3) * 4224;
#pragma unroll
            for (int kk = 0; kk < BK; kk += 8) {
                wmma::fragment<wmma::matrix_a, 16, 16, 8, wmma::precision::tf32, wmma::row_major> af[2];
                wmma::fragment<wmma::matrix_b, 16, 16, 8, wmma::precision::tf32, wmma::row_major> bf[4];
#pragma unroll
                for (int i = 0; i < 2; i++)
                    wmma::load_matrix_sync(af[i], Ac + (wm * 32 + i * 16) * LDA + kk, LDA);
#pragma unroll
                for (int j = 0; j < 4; j++)
                    wmma::load_matrix_sync(bf[j], Bc + kk * LDB + wn * 64 + j * 16, LDB);
#pragma unroll
                for (int i = 0; i < 2; i++)
#pragma unroll
                    for (int j = 0; j < 4; j++)
                        wmma::mma_sync(acc[i][j], af[i], bf[j], acc[i][j]);
            }
        }

        // epilogue: reuse B pool as Cs
        CP_WAIT0();
        __syncthreads();
        float* const Cs = Bbase;
#pragma unroll
        for (int i = 0; i < 2; i++)
#pragma unroll
            for (int j = 0; j < 4; j++)
                wmma::store_matrix_sync(Cs + (wm * 32 + i * 16) * LDC + wn * 64 + j * 16,
                                        acc[i][j], LDC, wmma::mem_row_major);
        __syncthreads();

#pragma unroll
        for (int it = 0; it < 16; it++) {
            int f = tid + it * 128;           // float4 index over 64x128
            int row = f >> 5;
            int col = (f & 31) * 4;
            int m = m0 + row;
            if (m < count) {
                const float* cr = Cs + row * LDC + col;
                float4 v;
                if (SPLIT) {
                    v.x = cr[0] * CORR; v.y = cr[1] * CORR;
                    v.z = cr[2] * CORR; v.w = cr[3] * CORR;
                } else {
                    v.x = cr[0] * CORR + bsm[col + 0];
                    v.y = cr[1] * CORR + bsm[col + 1];
                    v.z = cr[2] * CORR + bsm[col + 2];
                    v.w = cr[3] * CORR + bsm[col + 3];
                    if (RELU) {
                        v.x = fmaxf(v.x, 0.f); v.y = fmaxf(v.y, 0.f);
                        v.z = fmaxf(v.z, 0.f); v.w = fmaxf(v.w, 0.f);
                    }
                }
                *reinterpret_cast<float4*>(Out + (size_t)atb[row] * NTOT + n0 + col) = v;
            }
        }
        __syncthreads();
    }
}

// ---------------- kernel 4: reduce split-K halves + bias, weighted combine ----
__global__ void combine_kernel(const float* __restrict__ b2, float* __restrict__ out) {
    int t = blockIdx.x;
    float w[4];
    const float* bb[4];
#pragma unroll
    for (int s = 0; s < 4; s++) {
        w[s]  = d_w[t * 4 + s];
        bb[s] = b2 + (size_t)d_pid[t * 4 + s] * DIM;
    }
    for (int i = threadIdx.x; i < DIM; i += blockDim.x) {
        float acc = 0.f;
#pragma unroll
        for (int s = 0; s < 4; s++) {
            int asg = t * 4 + s;
            acc += w[s] * (d_Yp[0][asg][i] + d_Yp[1][asg][i] + bb[s][i]);
        }
        out[(size_t)t * DIM + i] = acc;
    }
}

// ---------------- launch ----------------
extern "C" void kernel_launch(void* const* d_in, const int* in_sizes, int n_in,
                              void* d_out, int out_size) {
    const float* x  = (const float*)d_in[0];
    const float* g1 = (const float*)d_in[1];
    const float* g2 = (const float*)d_in[2];
    const float* W1 = (const float*)d_in[3];
    const float* b1 = (const float*)d_in[4];
    const float* W2 = (const float*)d_in[5];
    const float* b2 = (const float*)d_in[6];
    float* out = (float*)d_out;

    cudaFuncSetAttribute(moe_gemm_wmma<DIM, DIM, HDIM, true, false>,
                         cudaFuncAttributeMaxDynamicSharedMemorySize, SMEM_DYN);
    cudaFuncSetAttribute(moe_gemm_wmma<DIM, HDIM, DIM, false, true>,
                         cudaFuncAttributeMaxDynamicSharedMemorySize, SMEM_DYN);

    zero_cnt_kernel<<<1, 64>>>();
    route_kernel<<<(TT * 32) / 128, 128>>>(x, g1, g2);
    // layer 1: [count,512] @ [512,1024] + b1, relu -> d_H            (512 CTAs)
    moe_gemm_wmma<DIM, DIM, HDIM, true, false>
        <<<dim3(HDIM / 128, NPAIR, 1), 128, SMEM_DYN>>>(x, W1, b1);
    // layer 2: [count,1024] @ [1024,512], split-K x2 -> d_Yp         (512 CTAs)
    moe_gemm_wmma<DIM, HDIM, DIM, false, true>
        <<<dim3(DIM / 128, NPAIR, 2), 128, SMEM_DYN>>>(x, W2, b2);
    combine_kernel<<<TT, 128>>>(b2, out);
}